// round 3
// baseline (speedup 1.0000x reference)
#include <cuda_runtime.h>
#include <cuda_bf16.h>

#define LEN 8192      // L
#define NROWS 8192    // B*C
#define NT 1024       // threads per CTA
#define SEG 8         // LEN / NT
#define GRID 144      // persistent CTAs
#define STRIDE (2 * GRID)

// Row-invariant coefficients (scratch via __device__ globals; no allocs)
__device__ float g_a[LEN];     // a[i] = -sup[i+1]/diag[i]  (a[L-1] = 0)
__device__ float g_rinv[LEN];  // 1/diag[i]

__global__ void ou_coef_kernel(const float* __restrict__ diag,
                               const float* __restrict__ sup) {
    int i = blockIdx.x * blockDim.x + threadIdx.x;
    if (i < LEN) {
        float rinv = 1.0f / diag[i];
        g_rinv[i] = rinv;
        float e = (i < LEN - 1) ? sup[i + 1] : 0.0f;
        g_a[i] = -e * rinv;
    }
}

// Persistent CTAs, TWO rows per iteration: amortizes the two CTA barriers
// over 2 rows, doubles memory in flight, and gives 2x ILP on the scan's
// serial FMA/shfl chains. Coefficients live in registers for the whole
// kernel (thread t always owns elements [8t, 8t+8)).
__global__ __launch_bounds__(NT, 1) void ou_solve_kernel(const float* __restrict__ z,
                                                         float* __restrict__ x) {
    __shared__ float aggA[2][32];
    __shared__ float aggB[2][32];
    __shared__ float inclB[2][32];

    const int tid  = threadIdx.x;
    const int lane = tid & 31;
    const int warp = tid >> 5;

    // Fixed-segment coefficients: registers, loaded once.
    const float4 ca0 = *(const float4*)(g_a    + tid * SEG);
    const float4 ca1 = *(const float4*)(g_a    + tid * SEG + 4);
    const float4 cr0 = *(const float4*)(g_rinv + tid * SEG);
    const float4 cr1 = *(const float4*)(g_rinv + tid * SEG + 4);

    const size_t tseg = (size_t)tid * SEG;

    for (int row0 = blockIdx.x; row0 < NROWS; row0 += STRIDE) {
        const int  row1 = row0 + GRID;
        const bool has1 = (row1 < NROWS);

        const float* zr0 = z + (size_t)row0 * LEN + tseg;
        const float* zr1 = z + (size_t)(has1 ? row1 : row0) * LEN + tseg;

        // ---- Load both rows (streaming) ----
        float4 u0 = __ldcs((const float4*)(zr0));
        float4 u1 = __ldcs((const float4*)(zr0 + 4));
        float4 v0 = __ldcs((const float4*)(zr1));
        float4 v1 = __ldcs((const float4*)(zr1 + 4));

        // ---- b = z / diag ----
        float p0 = u0.x * cr0.x, p1 = u0.y * cr0.y, p2 = u0.z * cr0.z, p3 = u0.w * cr0.w;
        float p4 = u1.x * cr1.x, p5 = u1.y * cr1.y, p6 = u1.z * cr1.z, p7 = u1.w * cr1.w;
        float q0 = v0.x * cr0.x, q1 = v0.y * cr0.y, q2 = v0.z * cr0.z, q3 = v0.w * cr0.w;
        float q4 = v1.x * cr1.x, q5 = v1.y * cr1.y, q6 = v1.z * cr1.z, q7 = v1.w * cr1.w;

        // ---- Segment composition (reverse): x[lo] = A*x[hi+1] + B ----
        // Four independent chains (A/B for each row) -> good ILP.
        float A0 = ca1.w, B0 = p7;
        float A1 = ca1.w, B1 = q7;
        B0 = fmaf(ca1.z, B0, p6); A0 *= ca1.z;  B1 = fmaf(ca1.z, B1, q6); A1 *= ca1.z;
        B0 = fmaf(ca1.y, B0, p5); A0 *= ca1.y;  B1 = fmaf(ca1.y, B1, q5); A1 *= ca1.y;
        B0 = fmaf(ca1.x, B0, p4); A0 *= ca1.x;  B1 = fmaf(ca1.x, B1, q4); A1 *= ca1.x;
        B0 = fmaf(ca0.w, B0, p3); A0 *= ca0.w;  B1 = fmaf(ca0.w, B1, q3); A1 *= ca0.w;
        B0 = fmaf(ca0.z, B0, p2); A0 *= ca0.z;  B1 = fmaf(ca0.z, B1, q2); A1 *= ca0.z;
        B0 = fmaf(ca0.y, B0, p1); A0 *= ca0.y;  B1 = fmaf(ca0.y, B1, q1); A1 *= ca0.y;
        B0 = fmaf(ca0.x, B0, p0); A0 *= ca0.x;  B1 = fmaf(ca0.x, B1, q0); A1 *= ca0.x;

        // ---- Warp reverse inclusive scan (both rows interleaved) ----
        float sA0 = A0, sB0 = B0, sA1 = A1, sB1 = B1;
        #pragma unroll
        for (int d = 1; d < 32; d <<= 1) {
            float a0 = __shfl_down_sync(0xffffffffu, sA0, d);
            float b0 = __shfl_down_sync(0xffffffffu, sB0, d);
            float a1 = __shfl_down_sync(0xffffffffu, sA1, d);
            float b1 = __shfl_down_sync(0xffffffffu, sB1, d);
            if (lane + d < 32) {
                sB0 = fmaf(sA0, b0, sB0); sA0 *= a0;
                sB1 = fmaf(sA1, b1, sB1); sA1 *= a1;
            }
        }
        if (lane == 0) {
            aggA[0][warp] = sA0; aggB[0][warp] = sB0;
            aggA[1][warp] = sA1; aggB[1][warp] = sB1;
        }
        __syncthreads();

        // ---- CTA-level scan: warp0 handles row0's aggregates, warp1 row1's ----
        if (warp < 2) {
            float gA = aggA[warp][lane], gB = aggB[warp][lane];
            #pragma unroll
            for (int d = 1; d < 32; d <<= 1) {
                float a2 = __shfl_down_sync(0xffffffffu, gA, d);
                float b2 = __shfl_down_sync(0xffffffffu, gB, d);
                if (lane + d < 32) {
                    gB = fmaf(gA, b2, gB);
                    gA = gA * a2;
                }
            }
            inclB[warp][lane] = gB;
        }
        __syncthreads();

        // ---- Boundary values ----
        float T0 = (warp < 31) ? inclB[0][warp + 1] : 0.0f;
        float T1 = (warp < 31) ? inclB[1][warp + 1] : 0.0f;
        float Bf0 = fmaf(sA0, T0, sB0);
        float Bf1 = fmaf(sA1, T1, sB1);
        float xv0 = __shfl_down_sync(0xffffffffu, Bf0, 1);
        float xv1 = __shfl_down_sync(0xffffffffu, Bf1, 1);
        if (lane == 31) { xv0 = T0; xv1 = T1; }

        // ---- Replay both segments; pack; store (streaming) ----
        float4 o0, o1, w0, w1;
        xv0 = fmaf(ca1.w, xv0, p7); o1.w = xv0;   xv1 = fmaf(ca1.w, xv1, q7); w1.w = xv1;
        xv0 = fmaf(ca1.z, xv0, p6); o1.z = xv0;   xv1 = fmaf(ca1.z, xv1, q6); w1.z = xv1;
        xv0 = fmaf(ca1.y, xv0, p5); o1.y = xv0;   xv1 = fmaf(ca1.y, xv1, q5); w1.y = xv1;
        xv0 = fmaf(ca1.x, xv0, p4); o1.x = xv0;   xv1 = fmaf(ca1.x, xv1, q4); w1.x = xv1;
        xv0 = fmaf(ca0.w, xv0, p3); o0.w = xv0;   xv1 = fmaf(ca0.w, xv1, q3); w0.w = xv1;
        xv0 = fmaf(ca0.z, xv0, p2); o0.z = xv0;   xv1 = fmaf(ca0.z, xv1, q2); w0.z = xv1;
        xv0 = fmaf(ca0.y, xv0, p1); o0.y = xv0;   xv1 = fmaf(ca0.y, xv1, q1); w0.y = xv1;
        xv0 = fmaf(ca0.x, xv0, p0); o0.x = xv0;   xv1 = fmaf(ca0.x, xv1, q0); w0.x = xv1;

        float* xr0 = x + (size_t)row0 * LEN + tseg;
        __stcs((float4*)(xr0),     o0);
        __stcs((float4*)(xr0 + 4), o1);
        if (has1) {
            float* xr1 = x + (size_t)row1 * LEN + tseg;
            __stcs((float4*)(xr1),     w0);
            __stcs((float4*)(xr1 + 4), w1);
        }
    }
}

extern "C" void kernel_launch(void* const* d_in, const int* in_sizes, int n_in,
                              void* d_out, int out_size) {
    const float* normal_samples = (const float*)d_in[0];  // (32, 256, 8192) f32
    const float* diag           = (const float*)d_in[1];  // (8192,) f32
    const float* sup            = (const float*)d_in[2];  // (8192,) f32
    float* out = (float*)d_out;

    (void)in_sizes; (void)n_in; (void)out_size;

    ou_coef_kernel<<<(LEN + 255) / 256, 256>>>(diag, sup);
    ou_solve_kernel<<<GRID, NT>>>(normal_samples, out);
}

// round 4
// speedup vs baseline: 1.2831x; 1.2831x over previous
#include <cuda_runtime.h>
#include <cuda_bf16.h>

#define LEN 8192      // L
#define NROWS 8192    // B*C
#define NT 1024       // threads per CTA
#define SEG 8         // LEN / NT

// Row-invariant coefficients (scratch via __device__ globals; no allocs)
__device__ float g_a[LEN];     // a[i] = -sup[i+1]/diag[i]  (a[L-1] = 0)
__device__ float g_rinv[LEN];  // 1/diag[i]

__global__ void ou_coef_kernel(const float* __restrict__ diag,
                               const float* __restrict__ sup) {
    int i = blockIdx.x * blockDim.x + threadIdx.x;
    if (i < LEN) {
        float rinv = 1.0f / diag[i];
        g_rinv[i] = rinv;
        float e = (i < LEN - 1) ? sup[i + 1] : 0.0f;
        g_a[i] = -e * rinv;
    }
}

// Persistent CTAs, one row per iteration (fits the 64-reg/thread budget at
// NT=1024 — two rows spills, measured R3). Coefficients live in registers for
// the whole kernel. CTA-level combine: every warp redundantly scans the 32
// warp aggregates itself -> ONE barrier per row, no warp0 serialization.
__global__ __launch_bounds__(NT, 1) void ou_solve_kernel(const float* __restrict__ z,
                                                         float* __restrict__ x) {
    __shared__ float aggA[32];
    __shared__ float aggB[32];

    const int tid  = threadIdx.x;
    const int lane = tid & 31;
    const int warp = tid >> 5;

    // Fixed-segment coefficients: registers, loaded once.
    const float4 ca0 = *(const float4*)(g_a    + tid * SEG);
    const float4 ca1 = *(const float4*)(g_a    + tid * SEG + 4);
    const float4 cr0 = *(const float4*)(g_rinv + tid * SEG);
    const float4 cr1 = *(const float4*)(g_rinv + tid * SEG + 4);

    const size_t tseg = (size_t)tid * SEG;
    const int stride = gridDim.x;

    // Prefetch first row's z.
    int row = blockIdx.x;
    float4 nz0, nz1;
    {
        const float* zr = z + (size_t)row * LEN + tseg;
        nz0 = __ldcs((const float4*)(zr));
        nz1 = __ldcs((const float4*)(zr + 4));
    }

    for (; row < NROWS; row += stride) {
        float4 z0 = nz0, z1 = nz1;
        // Prefetch next row early to cover DRAM latency across the scan.
        int nrow = row + stride;
        if (nrow < NROWS) {
            const float* zr = z + (size_t)nrow * LEN + tseg;
            nz0 = __ldcs((const float4*)(zr));
            nz1 = __ldcs((const float4*)(zr + 4));
        }

        // b[i] = z[i] / diag[i]
        float b0 = z0.x * cr0.x, b1 = z0.y * cr0.y, b2 = z0.z * cr0.z, b3 = z0.w * cr0.w;
        float b4 = z1.x * cr1.x, b5 = z1.y * cr1.y, b6 = z1.z * cr1.z, b7 = z1.w * cr1.w;

        // Segment composition (reverse): x[lo] = A * x[hi+1] + B.
        float A = ca1.w, B = b7;
        B = fmaf(ca1.z, B, b6); A *= ca1.z;
        B = fmaf(ca1.y, B, b5); A *= ca1.y;
        B = fmaf(ca1.x, B, b4); A *= ca1.x;
        B = fmaf(ca0.w, B, b3); A *= ca0.w;
        B = fmaf(ca0.z, B, b2); A *= ca0.z;
        B = fmaf(ca0.y, B, b1); A *= ca0.y;
        B = fmaf(ca0.x, B, b0); A *= ca0.x;

        // Warp reverse inclusive scan of affine maps: S(l) = M_l o ... o M_31
        float sA = A, sB = B;
        #pragma unroll
        for (int d = 1; d < 32; d <<= 1) {
            float A2 = __shfl_down_sync(0xffffffffu, sA, d);
            float B2 = __shfl_down_sync(0xffffffffu, sB, d);
            if (lane + d < 32) {
                sB = fmaf(sA, B2, sB);
                sA = sA * A2;
            }
        }
        if (lane == 0) { aggA[warp] = sA; aggB[warp] = sB; }
        __syncthreads();

        // EVERY warp scans the 32 aggregates itself (redundant but parallel):
        // removes the second barrier and the warp0-only serialization.
        float gA = aggA[lane], gB = aggB[lane];
        #pragma unroll
        for (int d = 1; d < 32; d <<= 1) {
            float A2 = __shfl_down_sync(0xffffffffu, gA, d);
            float B2 = __shfl_down_sync(0xffffffffu, gB, d);
            if (lane + d < 32) {
                gB = fmaf(gA, B2, gB);
                gA = gA * A2;
            }
        }
        // T_B = inclusive suffix B of warp aggregates starting at warp+1
        // (exclusive suffix for this warp, evaluated at 0).
        float T_B = __shfl_sync(0xffffffffu, gB, (warp < 31) ? (warp + 1) : 31);
        if (warp == 31) T_B = 0.0f;

        // Final scan value (B component) at this thread; boundary x entering
        // this segment is the final B of thread tid+1.
        float B_f = fmaf(sA, T_B, sB);
        float xv = __shfl_down_sync(0xffffffffu, B_f, 1);
        if (lane == 31) xv = T_B;   // next thread is lane0 of warp+1

        // Replay segment in registers; pack and store (streaming).
        float4 o0, o1;
        xv = fmaf(ca1.w, xv, b7); o1.w = xv;
        xv = fmaf(ca1.z, xv, b6); o1.z = xv;
        xv = fmaf(ca1.y, xv, b5); o1.y = xv;
        xv = fmaf(ca1.x, xv, b4); o1.x = xv;
        xv = fmaf(ca0.w, xv, b3); o0.w = xv;
        xv = fmaf(ca0.z, xv, b2); o0.z = xv;
        xv = fmaf(ca0.y, xv, b1); o0.y = xv;
        xv = fmaf(ca0.x, xv, b0); o0.x = xv;

        float* xr = x + (size_t)row * LEN + tseg;
        __stcs((float4*)(xr),     o0);
        __stcs((float4*)(xr + 4), o1);
        // Barrier before next iteration's lane0 writes into aggA/aggB, so no
        // warp can overwrite aggregates another warp hasn't consumed yet.
        __syncthreads();
    }
}

extern "C" void kernel_launch(void* const* d_in, const int* in_sizes, int n_in,
                              void* d_out, int out_size) {
    const float* normal_samples = (const float*)d_in[0];  // (32, 256, 8192) f32
    const float* diag           = (const float*)d_in[1];  // (8192,) f32
    const float* sup            = (const float*)d_in[2];  // (8192,) f32
    float* out = (float*)d_out;

    (void)in_sizes; (void)n_in; (void)out_size;

    // One persistent CTA per SM (148 on B300, 152 on GB300).
    int sm_count = 148;
    cudaDeviceGetAttribute(&sm_count, cudaDevAttrMultiProcessorCount, 0);

    ou_coef_kernel<<<(LEN + 255) / 256, 256>>>(diag, sup);
    ou_solve_kernel<<<sm_count, NT>>>(normal_samples, out);
}